// round 12
// baseline (speedup 1.0000x reference)
#include <cuda_runtime.h>
#include <cuda_fp16.h>
#include <stdint.h>

#define N_NODES 100000
#define N_EDGES 1600000
#define IN_DIM  128
#define HID_DIM 64
#define OUT_DIM 128

// Scratch (allocation-free rule: __device__ globals)
__device__ __align__(16) __half g_hs[(size_t)N_NODES * HID_DIM];   // fp16 messages
__device__ __align__(16) float  g_h2[(size_t)N_NODES * HID_DIM];   // relu'd hidden
__device__ int g_cnt[N_NODES];
__device__ int g_off[N_NODES];   // global exclusive scan of cnt
__device__ int g_pos[N_NODES];
__device__ int g_bpub[128];      // packed (sum | FLAG) per scan block
__device__ int g_csr[N_EDGES];
__device__ int g_sync;           // zero_cnt grid handshake (reset by scan_kernel)
__device__ int g_sync_release;

#define PUB_FLAG 0x40000000

// ---------------------------------------------------------------- f32x2 helpers
__device__ __forceinline__ unsigned long long pack2(float x, float y) {
    unsigned long long r;
    asm("mov.b64 %0, {%1,%2};" : "=l"(r) : "f"(x), "f"(y));
    return r;
}
__device__ __forceinline__ float2 unpack2(unsigned long long v) {
    float2 r;
    asm("mov.b64 {%0,%1}, %2;" : "=f"(r.x), "=f"(r.y) : "l"(v));
    return r;
}
__device__ __forceinline__ void ffma2(unsigned long long& d, unsigned long long a,
                                      unsigned long long b) {
    asm("fma.rn.f32x2 %0, %1, %2, %0;" : "+l"(d) : "l"(a), "l"(b));
}
__device__ __forceinline__ unsigned long long mul2(unsigned long long a,
                                                   unsigned long long b) {
    unsigned long long d;
    asm("mul.rn.f32x2 %0, %1, %2;" : "=l"(d) : "l"(a), "l"(b));
    return d;
}
__device__ __forceinline__ unsigned long long add2(unsigned long long a,
                                                   unsigned long long b) {
    unsigned long long d;
    asm("add.rn.f32x2 %0, %1, %2;" : "=l"(d) : "l"(a), "l"(b));
    return d;
}

// ---------------------------------------------------------------- zero + cnt
// One kernel, grid EXACTLY 148 blocks (all co-resident -> spin sync is safe).
__global__ __launch_bounds__(256) void zero_cnt_kernel(const int4* __restrict__ dst4,
                                                       int e, int n) {
    const int tid = blockIdx.x * blockDim.x + threadIdx.x;
    const int nthr = gridDim.x * blockDim.x;

    for (int i = tid; i < n; i += nthr) g_cnt[i] = 0;
    if (tid < 128) g_bpub[tid] = 0;

    __threadfence();
    __syncthreads();
    if (threadIdx.x == 0) {
        int arrived = atomicAdd(&g_sync, 1) + 1;
        if (arrived == (int)gridDim.x) atomicExch(&g_sync_release, 1);
        while (atomicAdd(&g_sync_release, 0) == 0) {}
    }
    __syncthreads();

    const int e4 = e >> 2;
    for (int i = tid; i < e4; i += nthr) {
        int4 d = dst4[i];
        atomicAdd(&g_cnt[d.x], 1);
        atomicAdd(&g_cnt[d.y], 1);
        atomicAdd(&g_cnt[d.z], 1);
        atomicAdd(&g_cnt[d.w], 1);
    }
    if (tid == 0) {
        const int* d1 = (const int*)dst4;
        for (int j = e4 * 4; j < e; j++) atomicAdd(&g_cnt[d1[j]], 1);
    }
}

// Single-pass exclusive scan (decoupled lookback; all blocks co-resident).
__global__ __launch_bounds__(1024) void scan_kernel(int n) {
    __shared__ int sh[1024];
    __shared__ int red[1024];
    const int t = threadIdx.x;
    const int b = blockIdx.x;
    const int i = b * 1024 + t;
    if (b == 0 && t == 0) { g_sync = 0; g_sync_release = 0; }  // reset handshake
    int v = (i < n) ? g_cnt[i] : 0;
    sh[t] = v;
    __syncthreads();
    #pragma unroll
    for (int d = 1; d < 1024; d <<= 1) {
        int u = (t >= d) ? sh[t - d] : 0;
        __syncthreads();
        sh[t] += u;
        __syncthreads();
    }
    int incl = sh[t];
    if (t == 1023) atomicExch(&g_bpub[b], incl | PUB_FLAG);

    int pv = 0;
    if (t < b) {
        int w;
        do { w = atomicAdd(&g_bpub[t], 0); } while ((w & PUB_FLAG) == 0);
        pv = w & (PUB_FLAG - 1);
    }
    red[t] = pv;
    __syncthreads();
    #pragma unroll
    for (int s = 512; s > 0; s >>= 1) {
        if (t < s) red[t] += red[t + s];
        __syncthreads();
    }
    int prefix = red[0];
    if (i < n) { g_off[i] = prefix + incl - v; g_pos[i] = 0; }
}

// ---------------------------------------------------------------- GEMM1 + fill
// Blocks [0, nGemm): hs[r][c] = fp16( rsqrt(cnt[r]+1) * sum_k x[r][k]*Wc[k][c] )
//   Tile M=128, N=64, K chunks of 32 (R8 synchronous structure — known good).
// Blocks [nGemm, ...): CSR fill, 4 edges/thread (overlaps with the GEMM).
__global__ __launch_bounds__(256) void gemm1_fill_kernel(const float* __restrict__ x,
                                                         const float* __restrict__ Wc,
                                                         const int* __restrict__ src,
                                                         const int* __restrict__ dst,
                                                         int n, int e, int nGemm) {
    __shared__ float4 Xs[128 * 9];
    __shared__ float4 Ws[32 * 16];

    if (blockIdx.x >= nGemm) {   // ---- fill part
        int i = (blockIdx.x - nGemm) * 256 + threadIdx.x;
        int e4 = e >> 2;
        if (i < e4) {
            int4 s4 = ((const int4*)src)[i];
            int4 d4 = ((const int4*)dst)[i];
            int p;
            p = g_off[d4.x] + atomicAdd(&g_pos[d4.x], 1); g_csr[p] = s4.x;
            p = g_off[d4.y] + atomicAdd(&g_pos[d4.y], 1); g_csr[p] = s4.y;
            p = g_off[d4.z] + atomicAdd(&g_pos[d4.z], 1); g_csr[p] = s4.z;
            p = g_off[d4.w] + atomicAdd(&g_pos[d4.w], 1); g_csr[p] = s4.w;
        }
        if (i == 0) {
            for (int j = e4 * 4; j < e; j++) {
                int d = dst[j];
                int p = g_off[d] + atomicAdd(&g_pos[d], 1);
                g_csr[p] = src[j];
            }
        }
        return;
    }

    const int t = threadIdx.x;
    const int rowBase = blockIdx.x * 128;
    const int tr = t & 31;
    const int tc = t >> 5;

    unsigned long long acc[4][4];
    #pragma unroll
    for (int i = 0; i < 4; i++)
        #pragma unroll
        for (int c2 = 0; c2 < 4; c2++) acc[i][c2] = 0ull;

    const float4* Xg = (const float4*)x;
    const float4* Wg = (const float4*)Wc;

    for (int c = 0; c < 4; c++) {
        #pragma unroll
        for (int i = 0; i < 2; i++) {
            int idx = t + i * 256;
            int k = idx >> 4, col4 = idx & 15;
            Ws[idx] = Wg[(c * 32 + k) * 16 + col4];
        }
        #pragma unroll
        for (int i = 0; i < 4; i++) {
            int idx = t + i * 256;
            int r = idx >> 3, q = idx & 7;
            int row = rowBase + r;
            float4 v = make_float4(0.f, 0.f, 0.f, 0.f);
            if (row < n) v = Xg[(size_t)row * 32 + c * 8 + q];
            Xs[r * 9 + q] = v;
        }
        __syncthreads();

        #pragma unroll
        for (int kq = 0; kq < 8; kq++) {
            float4 xv[4];
            #pragma unroll
            for (int i = 0; i < 4; i++) xv[i] = Xs[(tr + 32 * i) * 9 + kq];
            #pragma unroll
            for (int kk = 0; kk < 4; kk++) {
                float4 w0 = Ws[(kq * 4 + kk) * 16 + tc * 2];
                float4 w1 = Ws[(kq * 4 + kk) * 16 + tc * 2 + 1];
                unsigned long long wp0 = pack2(w0.x, w0.y);
                unsigned long long wp1 = pack2(w0.z, w0.w);
                unsigned long long wp2 = pack2(w1.x, w1.y);
                unsigned long long wp3 = pack2(w1.z, w1.w);
                #pragma unroll
                for (int i = 0; i < 4; i++) {
                    float s = (kk == 0) ? xv[i].x : (kk == 1) ? xv[i].y
                            : (kk == 2) ? xv[i].z : xv[i].w;
                    unsigned long long ss = pack2(s, s);
                    ffma2(acc[i][0], ss, wp0);
                    ffma2(acc[i][1], ss, wp1);
                    ffma2(acc[i][2], ss, wp2);
                    ffma2(acc[i][3], ss, wp3);
                }
            }
        }
        __syncthreads();
    }

    #pragma unroll
    for (int i = 0; i < 4; i++) {
        int row = rowBase + tr + 32 * i;
        if (row < n) {
            float dv = rsqrtf((float)g_cnt[row] + 1.0f);
            unsigned long long dd = pack2(dv, dv);
            float2 a = unpack2(mul2(acc[i][0], dd));
            float2 b = unpack2(mul2(acc[i][1], dd));
            float2 cc = unpack2(mul2(acc[i][2], dd));
            float2 d = unpack2(mul2(acc[i][3], dd));
            __half2 h0 = __floats2half2_rn(a.x, a.y);
            __half2 h1 = __floats2half2_rn(b.x, b.y);
            __half2 h2 = __floats2half2_rn(cc.x, cc.y);
            __half2 h3 = __floats2half2_rn(d.x, d.y);
            uint4 pk;
            pk.x = *(unsigned int*)&h0;
            pk.y = *(unsigned int*)&h1;
            pk.z = *(unsigned int*)&h2;
            pk.w = *(unsigned int*)&h3;
            ((uint4*)g_hs)[(size_t)row * 8 + tc] = pk;
        }
    }
}

// ---------------------------------------------------------------- aggregate
// 8 threads/node, 32 nodes/block, no smem -> high occupancy hides L2 latency.
// h2 = relu(dinv * (self + sum neighbors) + bconv), fp32 -> g_h2.
__global__ __launch_bounds__(256) void agg_kernel(const float* __restrict__ bconv,
                                                  int n) {
    const int t = threadIdx.x;
    const int node = blockIdx.x * 32 + (t >> 3);
    const int c8 = t & 7;        // uint4 chunk: floats [c8*8, c8*8+8)
    if (node >= n) return;

    const uint4* hs4 = (const uint4*)g_hs;
    float a[8] = {0,0,0,0,0,0,0,0};
    float b[8] = {0,0,0,0,0,0,0,0};
    {   // self-loop
        uint4 v = hs4[(size_t)node * 8 + c8];
        const __half2* hp = (const __half2*)&v;
        #pragma unroll
        for (int m = 0; m < 4; m++) {
            float2 f = __half22float2(hp[m]);
            a[m * 2] += f.x; a[m * 2 + 1] += f.y;
        }
    }
    int cnt = g_cnt[node];
    int beg = g_off[node];
    int end = beg + cnt;
    int j = beg;
    for (; j + 3 < end; j += 4) {
        int s0 = g_csr[j],     s1 = g_csr[j + 1];
        int s2 = g_csr[j + 2], s3 = g_csr[j + 3];
        uint4 v0 = hs4[(size_t)s0 * 8 + c8];
        uint4 v1 = hs4[(size_t)s1 * 8 + c8];
        uint4 v2 = hs4[(size_t)s2 * 8 + c8];
        uint4 v3 = hs4[(size_t)s3 * 8 + c8];
        const __half2* h0 = (const __half2*)&v0;
        const __half2* h1 = (const __half2*)&v1;
        const __half2* h2 = (const __half2*)&v2;
        const __half2* h3 = (const __half2*)&v3;
        #pragma unroll
        for (int m = 0; m < 4; m++) {
            float2 f0 = __half22float2(h0[m]);
            float2 f1 = __half22float2(h1[m]);
            float2 f2 = __half22float2(h2[m]);
            float2 f3 = __half22float2(h3[m]);
            a[m * 2] += f0.x + f2.x; a[m * 2 + 1] += f0.y + f2.y;
            b[m * 2] += f1.x + f3.x; b[m * 2 + 1] += f1.y + f3.y;
        }
    }
    for (; j < end; j++) {
        int s0 = g_csr[j];
        uint4 v0 = hs4[(size_t)s0 * 8 + c8];
        const __half2* h0 = (const __half2*)&v0;
        #pragma unroll
        for (int m = 0; m < 4; m++) {
            float2 f0 = __half22float2(h0[m]);
            a[m * 2] += f0.x; a[m * 2 + 1] += f0.y;
        }
    }
    float dv = rsqrtf((float)cnt + 1.0f);
    float4 bcv0 = __ldg((const float4*)&bconv[c8 * 8]);
    float4 bcv1 = __ldg((const float4*)&bconv[c8 * 8 + 4]);
    float4 r0, r1;
    r0.x = fmaxf(fmaf(a[0] + b[0], dv, bcv0.x), 0.f);
    r0.y = fmaxf(fmaf(a[1] + b[1], dv, bcv0.y), 0.f);
    r0.z = fmaxf(fmaf(a[2] + b[2], dv, bcv0.z), 0.f);
    r0.w = fmaxf(fmaf(a[3] + b[3], dv, bcv0.w), 0.f);
    r1.x = fmaxf(fmaf(a[4] + b[4], dv, bcv1.x), 0.f);
    r1.y = fmaxf(fmaf(a[5] + b[5], dv, bcv1.y), 0.f);
    r1.z = fmaxf(fmaf(a[6] + b[6], dv, bcv1.z), 0.f);
    r1.w = fmaxf(fmaf(a[7] + b[7], dv, bcv1.w), 0.f);
    ((float4*)g_h2)[(size_t)node * 16 + c8 * 2]     = r0;
    ((float4*)g_h2)[(size_t)node * 16 + c8 * 2 + 1] = r1;
}

// ---------------------------------------------------------------- GEMM2
// out = h2 @ Wlin + blin.  Tile M=64, N=128, K=64 in 2 chunks of 32.
// 256 threads = 8 warps; warp tc owns cols [tc*16, tc*16+16); lane tr rows {tr, tr+32}.
__global__ __launch_bounds__(256) void gemm2_kernel(const float* __restrict__ Wlin,
                                                    const float* __restrict__ blin,
                                                    float* __restrict__ out,
                                                    int n) {
    __shared__ float4 Hs[64 * 9];    // 9 KB
    __shared__ float4 Ws[32 * 32];   // 16 KB
    const int t = threadIdx.x;
    const int rowBase = blockIdx.x * 64;
    const int tr = t & 31;
    const int tc = t >> 5;

    unsigned long long acc[2][8];
    #pragma unroll
    for (int i = 0; i < 2; i++)
        #pragma unroll
        for (int c2 = 0; c2 < 8; c2++) acc[i][c2] = 0ull;

    const float4* Wg = (const float4*)Wlin;
    const float4* Hg = (const float4*)g_h2;

    for (int c = 0; c < 2; c++) {
        if (c) __syncthreads();
        #pragma unroll
        for (int i = 0; i < 4; i++) {
            int idx = t + i * 256;
            int k = idx >> 5, col4 = idx & 31;
            Ws[idx] = Wg[(c * 32 + k) * 32 + col4];
        }
        #pragma unroll
        for (int i = 0; i < 2; i++) {
            int idx = t + i * 256;
            int r = idx >> 3, q = idx & 7;
            int row = rowBase + r;
            float4 v = make_float4(0.f, 0.f, 0.f, 0.f);
            if (row < n) v = Hg[(size_t)row * 16 + c * 8 + q];
            Hs[r * 9 + q] = v;
        }
        __syncthreads();

        #pragma unroll
        for (int kq = 0; kq < 8; kq++) {
            float4 xv[2];
            #pragma unroll
            for (int i = 0; i < 2; i++) xv[i] = Hs[(tr + 32 * i) * 9 + kq];
            #pragma unroll
            for (int kk = 0; kk < 4; kk++) {
                unsigned long long wp[8];
                #pragma unroll
                for (int m = 0; m < 4; m++) {
                    float4 w = Ws[(kq * 4 + kk) * 32 + tc * 4 + m];
                    wp[m * 2]     = pack2(w.x, w.y);
                    wp[m * 2 + 1] = pack2(w.z, w.w);
                }
                #pragma unroll
                for (int i = 0; i < 2; i++) {
                    float s = (kk == 0) ? xv[i].x : (kk == 1) ? xv[i].y
                            : (kk == 2) ? xv[i].z : xv[i].w;
                    unsigned long long ss = pack2(s, s);
                    #pragma unroll
                    for (int c2 = 0; c2 < 8; c2++) ffma2(acc[i][c2], ss, wp[c2]);
                }
            }
        }
    }

    unsigned long long blp[8];
    #pragma unroll
    for (int m = 0; m < 4; m++) {
        float4 b = __ldg((const float4*)&blin[tc * 16 + m * 4]);
        blp[m * 2]     = pack2(b.x, b.y);
        blp[m * 2 + 1] = pack2(b.z, b.w);
    }
    #pragma unroll
    for (int i = 0; i < 2; i++) {
        int row = rowBase + tr + 32 * i;
        if (row < n) {
            size_t off = (size_t)row * 32 + tc * 4;
            #pragma unroll
            for (int m = 0; m < 4; m++) {
                float2 lo = unpack2(add2(acc[i][m * 2],     blp[m * 2]));
                float2 hi = unpack2(add2(acc[i][m * 2 + 1], blp[m * 2 + 1]));
                ((float4*)out)[off + m] = make_float4(lo.x, lo.y, hi.x, hi.y);
            }
        }
    }
}

// ---------------------------------------------------------------- launch
extern "C" void kernel_launch(void* const* d_in, const int* in_sizes, int n_in,
                              void* d_out, int out_size) {
    const float* x  = (const float*)d_in[0];
    const int*   ei = (const int*)  d_in[1];
    const float* Wc = (const float*)d_in[2];
    const float* bc = (const float*)d_in[3];
    const float* Wl = (const float*)d_in[4];
    const float* bl = (const float*)d_in[5];
    float*       out = (float*)d_out;

    const int n = in_sizes[0] / IN_DIM;      // 100000
    const int e = in_sizes[1] / 2;           // 1600000
    const int* src = ei;
    const int* dst = ei + e;
    const int nb = (n + 1023) >> 10;         // 98 (must be <= 128)

    zero_cnt_kernel<<<148, 256>>>((const int4*)dst, e, n);
    scan_kernel<<<nb, 1024>>>(n);
    {
        int nGemm = (n + 127) / 128;
        int nFill = ((e >> 2) + 255) / 256;
        gemm1_fill_kernel<<<nGemm + nFill, 256>>>(x, Wc, src, dst, n, e, nGemm);
    }
    agg_kernel  <<<(n + 31) / 32, 256>>>(bc, n);
    gemm2_kernel<<<(n + 63) / 64, 256>>>(Wl, bl, out, n);
}

// round 13
// speedup vs baseline: 1.0931x; 1.0931x over previous
#include <cuda_runtime.h>
#include <cuda_fp16.h>
#include <stdint.h>

#define N_NODES 100000
#define N_EDGES 1600000
#define IN_DIM  128
#define HID_DIM 64
#define OUT_DIM 128

// Scratch (allocation-free rule: __device__ globals)
__device__ __align__(16) __half g_hs[(size_t)N_NODES * HID_DIM];   // fp16 messages
__device__ __align__(16) float  g_h2[(size_t)N_NODES * HID_DIM];   // relu'd hidden
__device__ int g_cnt[N_NODES];
__device__ int g_off[N_NODES];   // global exclusive scan of cnt
__device__ int g_pos[N_NODES];
__device__ int g_bpub[128];      // packed (sum | FLAG) per scan block
__device__ int g_csr[N_EDGES];

#define PUB_FLAG 0x40000000

// ---------------------------------------------------------------- f32x2 helpers
__device__ __forceinline__ unsigned long long pack2(float x, float y) {
    unsigned long long r;
    asm("mov.b64 %0, {%1,%2};" : "=l"(r) : "f"(x), "f"(y));
    return r;
}
__device__ __forceinline__ float2 unpack2(unsigned long long v) {
    float2 r;
    asm("mov.b64 {%0,%1}, %2;" : "=f"(r.x), "=f"(r.y) : "l"(v));
    return r;
}
__device__ __forceinline__ void ffma2(unsigned long long& d, unsigned long long a,
                                      unsigned long long b) {
    asm("fma.rn.f32x2 %0, %1, %2, %0;" : "+l"(d) : "l"(a), "l"(b));
}
__device__ __forceinline__ unsigned long long mul2(unsigned long long a,
                                                   unsigned long long b) {
    unsigned long long d;
    asm("mul.rn.f32x2 %0, %1, %2;" : "=l"(d) : "l"(a), "l"(b));
    return d;
}
__device__ __forceinline__ unsigned long long add2(unsigned long long a,
                                                   unsigned long long b) {
    unsigned long long d;
    asm("add.rn.f32x2 %0, %1, %2;" : "=l"(d) : "l"(a), "l"(b));
    return d;
}

// ---------------------------------------------------------------- CSR build
__global__ void zero_kernel(int n) {
    int i = blockIdx.x * blockDim.x + threadIdx.x;
    if (i < n) g_cnt[i] = 0;
    if (i < 128) g_bpub[i] = 0;
}

__global__ void cnt_kernel(const int4* __restrict__ dst4, int e) {
    int i = blockIdx.x * blockDim.x + threadIdx.x;
    int e4 = e >> 2;
    if (i < e4) {
        int4 d = dst4[i];
        atomicAdd(&g_cnt[d.x], 1);
        atomicAdd(&g_cnt[d.y], 1);
        atomicAdd(&g_cnt[d.z], 1);
        atomicAdd(&g_cnt[d.w], 1);
    }
    if (i == 0) {
        const int* d1 = (const int*)dst4;
        for (int j = e4 * 4; j < e; j++) atomicAdd(&g_cnt[d1[j]], 1);
    }
}

// Single-pass exclusive scan (decoupled lookback; all blocks co-resident).
__global__ __launch_bounds__(1024) void scan_kernel(int n) {
    __shared__ int sh[1024];
    __shared__ int red[1024];
    const int t = threadIdx.x;
    const int b = blockIdx.x;
    const int i = b * 1024 + t;
    int v = (i < n) ? g_cnt[i] : 0;
    sh[t] = v;
    __syncthreads();
    #pragma unroll
    for (int d = 1; d < 1024; d <<= 1) {
        int u = (t >= d) ? sh[t - d] : 0;
        __syncthreads();
        sh[t] += u;
        __syncthreads();
    }
    int incl = sh[t];
    if (t == 1023) atomicExch(&g_bpub[b], incl | PUB_FLAG);

    int pv = 0;
    if (t < b) {
        int w;
        do { w = atomicAdd(&g_bpub[t], 0); } while ((w & PUB_FLAG) == 0);
        pv = w & (PUB_FLAG - 1);
    }
    red[t] = pv;
    __syncthreads();
    #pragma unroll
    for (int s = 512; s > 0; s >>= 1) {
        if (t < s) red[t] += red[t + s];
        __syncthreads();
    }
    int prefix = red[0];
    if (i < n) { g_off[i] = prefix + incl - v; g_pos[i] = 0; }
}

// ---------------------------------------------------------------- GEMM1 + fill
// Blocks [0, nGemm): hs[r][c] = fp16( rsqrt(cnt[r]+1) * sum_k x[r][k]*Wc[k][c] )
//   M=128 tile, N=64, K in 4 chunks of 32. Register-staged double buffer:
//   LDG chunk c+1 into regs while computing chunk c; STS at iter top.
// Blocks [nGemm, ...): CSR fill, 4 edges/thread (overlaps with the GEMM).
// Dynamic smem: Xs[2][1152] + Ws[2][512] float4 = 52 KB.
__global__ __launch_bounds__(256) void gemm1_fill_kernel(const float* __restrict__ x,
                                                         const float* __restrict__ Wc,
                                                         const int* __restrict__ src,
                                                         const int* __restrict__ dst,
                                                         int n, int e, int nGemm) {
    extern __shared__ float4 smem[];
    float4* Xs = smem;                 // [2][128*9]
    float4* Ws = smem + 2 * 1152;      // [2][512]

    if (blockIdx.x >= nGemm) {   // ---- fill part (no smem use)
        int i = (blockIdx.x - nGemm) * 256 + threadIdx.x;
        int e4 = e >> 2;
        if (i < e4) {
            int4 s4 = ((const int4*)src)[i];
            int4 d4 = ((const int4*)dst)[i];
            int p;
            p = g_off[d4.x] + atomicAdd(&g_pos[d4.x], 1); g_csr[p] = s4.x;
            p = g_off[d4.y] + atomicAdd(&g_pos[d4.y], 1); g_csr[p] = s4.y;
            p = g_off[d4.z] + atomicAdd(&g_pos[d4.z], 1); g_csr[p] = s4.z;
            p = g_off[d4.w] + atomicAdd(&g_pos[d4.w], 1); g_csr[p] = s4.w;
        }
        if (i == 0) {
            for (int j = e4 * 4; j < e; j++) {
                int d = dst[j];
                int p = g_off[d] + atomicAdd(&g_pos[d], 1);
                g_csr[p] = src[j];
            }
        }
        return;
    }

    const int t = threadIdx.x;
    const int rowBase = blockIdx.x * 128;
    const int tr = t & 31;
    const int tc = t >> 5;

    const float4* Xg = (const float4*)x;
    const float4* Wg = (const float4*)Wc;   // chunk c, elem idx -> Wg[c*512 + idx]

    // per-thread X sources (row clamped; clamped rows never stored)
    int xr[4], xq[4];
    const float4* xsrc[4];
    #pragma unroll
    for (int i = 0; i < 4; i++) {
        int idx = t + i * 256;
        xr[i] = idx >> 3; xq[i] = idx & 7;
        int row = rowBase + xr[i];
        if (row >= n) row = n - 1;
        xsrc[i] = Xg + (size_t)row * 32 + xq[i];
    }

    unsigned long long acc[4][4];
    #pragma unroll
    for (int i = 0; i < 4; i++)
        #pragma unroll
        for (int c2 = 0; c2 < 4; c2++) acc[i][c2] = 0ull;

    // prologue: stage chunk 0 in registers
    float4 wreg0 = Wg[t];
    float4 wreg1 = Wg[t + 256];
    float4 xreg[4];
    #pragma unroll
    for (int i = 0; i < 4; i++) xreg[i] = xsrc[i][0];

    #pragma unroll
    for (int c = 0; c < 4; c++) {
        float4* Xb = Xs + (c & 1) * 1152;
        float4* Wb = Ws + (c & 1) * 512;
        __syncthreads();   // all warps done reading buffer (c-2) / computing (c-1)
        Wb[t]       = wreg0;
        Wb[t + 256] = wreg1;
        #pragma unroll
        for (int i = 0; i < 4; i++) Xb[xr[i] * 9 + xq[i]] = xreg[i];
        // prefetch chunk c+1 (issued before barrier; latency hidden by compute)
        if (c < 3) {
            wreg0 = Wg[(c + 1) * 512 + t];
            wreg1 = Wg[(c + 1) * 512 + t + 256];
            #pragma unroll
            for (int i = 0; i < 4; i++) xreg[i] = xsrc[i][(c + 1) * 8];
        }
        __syncthreads();   // buffer published

        #pragma unroll
        for (int kq = 0; kq < 8; kq++) {
            float4 xv[4];
            #pragma unroll
            for (int i = 0; i < 4; i++) xv[i] = Xb[(tr + 32 * i) * 9 + kq];
            #pragma unroll
            for (int kk = 0; kk < 4; kk++) {
                float4 w0 = Wb[(kq * 4 + kk) * 16 + tc * 2];
                float4 w1 = Wb[(kq * 4 + kk) * 16 + tc * 2 + 1];
                unsigned long long wp0 = pack2(w0.x, w0.y);
                unsigned long long wp1 = pack2(w0.z, w0.w);
                unsigned long long wp2 = pack2(w1.x, w1.y);
                unsigned long long wp3 = pack2(w1.z, w1.w);
                #pragma unroll
                for (int i = 0; i < 4; i++) {
                    float s = (kk == 0) ? xv[i].x : (kk == 1) ? xv[i].y
                            : (kk == 2) ? xv[i].z : xv[i].w;
                    unsigned long long ss = pack2(s, s);
                    ffma2(acc[i][0], ss, wp0);
                    ffma2(acc[i][1], ss, wp1);
                    ffma2(acc[i][2], ss, wp2);
                    ffma2(acc[i][3], ss, wp3);
                }
            }
        }
    }

    #pragma unroll
    for (int i = 0; i < 4; i++) {
        int row = rowBase + tr + 32 * i;
        if (row < n) {
            float dv = rsqrtf((float)g_cnt[row] + 1.0f);
            unsigned long long dd = pack2(dv, dv);
            float2 a = unpack2(mul2(acc[i][0], dd));
            float2 b = unpack2(mul2(acc[i][1], dd));
            float2 cc = unpack2(mul2(acc[i][2], dd));
            float2 d = unpack2(mul2(acc[i][3], dd));
            __half2 h0 = __floats2half2_rn(a.x, a.y);
            __half2 h1 = __floats2half2_rn(b.x, b.y);
            __half2 h2 = __floats2half2_rn(cc.x, cc.y);
            __half2 h3 = __floats2half2_rn(d.x, d.y);
            uint4 pk;
            pk.x = *(unsigned int*)&h0;
            pk.y = *(unsigned int*)&h1;
            pk.z = *(unsigned int*)&h2;
            pk.w = *(unsigned int*)&h3;
            ((uint4*)g_hs)[(size_t)row * 8 + tc] = pk;
        }
    }
}

// ---------------------------------------------------------------- aggregate
// 8 threads/node, 32 nodes/block, no smem. 4-deep gathers summed pairwise in
// fp16 (HADD2 tree), converted once, accumulated fp32.
__global__ __launch_bounds__(256) void agg_kernel(const float* __restrict__ bconv,
                                                  int n) {
    const int t = threadIdx.x;
    const int node = blockIdx.x * 32 + (t >> 3);
    const int c8 = t & 7;        // uint4 chunk: floats [c8*8, c8*8+8)
    if (node >= n) return;

    const uint4* hs4 = (const uint4*)g_hs;
    float a[8] = {0,0,0,0,0,0,0,0};
    {   // self-loop (fp32 path)
        uint4 v = hs4[(size_t)node * 8 + c8];
        const __half2* hp = (const __half2*)&v;
        #pragma unroll
        for (int m = 0; m < 4; m++) {
            float2 f = __half22float2(hp[m]);
            a[m * 2] += f.x; a[m * 2 + 1] += f.y;
        }
    }
    int cnt = g_cnt[node];
    int beg = g_off[node];
    int end = beg + cnt;
    int j = beg;
    for (; j + 3 < end; j += 4) {
        int s0 = g_csr[j],     s1 = g_csr[j + 1];
        int s2 = g_csr[j + 2], s3 = g_csr[j + 3];
        uint4 v0 = hs4[(size_t)s0 * 8 + c8];
        uint4 v1 = hs4[(size_t)s1 * 8 + c8];
        uint4 v2 = hs4[(size_t)s2 * 8 + c8];
        uint4 v3 = hs4[(size_t)s3 * 8 + c8];
        const __half2* h0 = (const __half2*)&v0;
        const __half2* h1 = (const __half2*)&v1;
        const __half2* h2 = (const __half2*)&v2;
        const __half2* h3 = (const __half2*)&v3;
        #pragma unroll
        for (int m = 0; m < 4; m++) {
            __half2 s01 = __hadd2(h0[m], h1[m]);
            __half2 s23 = __hadd2(h2[m], h3[m]);
            float2 f = __half22float2(__hadd2(s01, s23));
            a[m * 2] += f.x; a[m * 2 + 1] += f.y;
        }
    }
    for (; j < end; j++) {
        int s0 = g_csr[j];
        uint4 v0 = hs4[(size_t)s0 * 8 + c8];
        const __half2* h0 = (const __half2*)&v0;
        #pragma unroll
        for (int m = 0; m < 4; m++) {
            float2 f0 = __half22float2(h0[m]);
            a[m * 2] += f0.x; a[m * 2 + 1] += f0.y;
        }
    }
    float dv = rsqrtf((float)cnt + 1.0f);
    float4 bcv0 = __ldg((const float4*)&bconv[c8 * 8]);
    float4 bcv1 = __ldg((const float4*)&bconv[c8 * 8 + 4]);
    float4 r0, r1;
    r0.x = fmaxf(fmaf(a[0], dv, bcv0.x), 0.f);
    r0.y = fmaxf(fmaf(a[1], dv, bcv0.y), 0.f);
    r0.z = fmaxf(fmaf(a[2], dv, bcv0.z), 0.f);
    r0.w = fmaxf(fmaf(a[3], dv, bcv0.w), 0.f);
    r1.x = fmaxf(fmaf(a[4], dv, bcv1.x), 0.f);
    r1.y = fmaxf(fmaf(a[5], dv, bcv1.y), 0.f);
    r1.z = fmaxf(fmaf(a[6], dv, bcv1.z), 0.f);
    r1.w = fmaxf(fmaf(a[7], dv, bcv1.w), 0.f);
    ((float4*)g_h2)[(size_t)node * 16 + c8 * 2]     = r0;
    ((float4*)g_h2)[(size_t)node * 16 + c8 * 2 + 1] = r1;
}

// ---------------------------------------------------------------- GEMM2
// out = h2 @ Wlin + blin.  Tile M=64, N=128, K=64 in 2 chunks of 32.
__global__ __launch_bounds__(256) void gemm2_kernel(const float* __restrict__ Wlin,
                                                    const float* __restrict__ blin,
                                                    float* __restrict__ out,
                                                    int n) {
    __shared__ float4 Hs[64 * 9];    // 9 KB
    __shared__ float4 Ws[32 * 32];   // 16 KB
    const int t = threadIdx.x;
    const int rowBase = blockIdx.x * 64;
    const int tr = t & 31;
    const int tc = t >> 5;

    unsigned long long acc[2][8];
    #pragma unroll
    for (int i = 0; i < 2; i++)
        #pragma unroll
        for (int c2 = 0; c2 < 8; c2++) acc[i][c2] = 0ull;

    const float4* Wg = (const float4*)Wlin;
    const float4* Hg = (const float4*)g_h2;

    for (int c = 0; c < 2; c++) {
        if (c) __syncthreads();
        #pragma unroll
        for (int i = 0; i < 4; i++) {
            int idx = t + i * 256;
            int k = idx >> 5, col4 = idx & 31;
            Ws[idx] = Wg[(c * 32 + k) * 32 + col4];
        }
        #pragma unroll
        for (int i = 0; i < 2; i++) {
            int idx = t + i * 256;
            int r = idx >> 3, q = idx & 7;
            int row = rowBase + r;
            float4 v = make_float4(0.f, 0.f, 0.f, 0.f);
            if (row < n) v = Hg[(size_t)row * 16 + c * 8 + q];
            Hs[r * 9 + q] = v;
        }
        __syncthreads();

        #pragma unroll
        for (int kq = 0; kq < 8; kq++) {
            float4 xv[2];
            #pragma unroll
            for (int i = 0; i < 2; i++) xv[i] = Hs[(tr + 32 * i) * 9 + kq];
            #pragma unroll
            for (int kk = 0; kk < 4; kk++) {
                unsigned long long wp[8];
                #pragma unroll
                for (int m = 0; m < 4; m++) {
                    float4 w = Ws[(kq * 4 + kk) * 32 + tc * 4 + m];
                    wp[m * 2]     = pack2(w.x, w.y);
                    wp[m * 2 + 1] = pack2(w.z, w.w);
                }
                #pragma unroll
                for (int i = 0; i < 2; i++) {
                    float s = (kk == 0) ? xv[i].x : (kk == 1) ? xv[i].y
                            : (kk == 2) ? xv[i].z : xv[i].w;
                    unsigned long long ss = pack2(s, s);
                    #pragma unroll
                    for (int c2 = 0; c2 < 8; c2++) ffma2(acc[i][c2], ss, wp[c2]);
                }
            }
        }
    }

    unsigned long long blp[8];
    #pragma unroll
    for (int m = 0; m < 4; m++) {
        float4 b = __ldg((const float4*)&blin[tc * 16 + m * 4]);
        blp[m * 2]     = pack2(b.x, b.y);
        blp[m * 2 + 1] = pack2(b.z, b.w);
    }
    #pragma unroll
    for (int i = 0; i < 2; i++) {
        int row = rowBase + tr + 32 * i;
        if (row < n) {
            size_t off = (size_t)row * 32 + tc * 4;
            #pragma unroll
            for (int m = 0; m < 4; m++) {
                float2 lo = unpack2(add2(acc[i][m * 2],     blp[m * 2]));
                float2 hi = unpack2(add2(acc[i][m * 2 + 1], blp[m * 2 + 1]));
                ((float4*)out)[off + m] = make_float4(lo.x, lo.y, hi.x, hi.y);
            }
        }
    }
}

// ---------------------------------------------------------------- launch
extern "C" void kernel_launch(void* const* d_in, const int* in_sizes, int n_in,
                              void* d_out, int out_size) {
    const float* x  = (const float*)d_in[0];
    const int*   ei = (const int*)  d_in[1];
    const float* Wc = (const float*)d_in[2];
    const float* bc = (const float*)d_in[3];
    const float* Wl = (const float*)d_in[4];
    const float* bl = (const float*)d_in[5];
    float*       out = (float*)d_out;

    const int n = in_sizes[0] / IN_DIM;      // 100000
    const int e = in_sizes[1] / 2;           // 1600000
    const int* src = ei;
    const int* dst = ei + e;
    const int nb = (n + 1023) >> 10;         // 98 (must be <= 128)

    const int SMEM1 = (2 * 1152 + 2 * 512) * 16;   // 53248 B
    cudaFuncSetAttribute(gemm1_fill_kernel,
                         cudaFuncAttributeMaxDynamicSharedMemorySize, SMEM1);

    zero_kernel<<<(n + 255) / 256, 256>>>(n);
    cnt_kernel <<<((e >> 2) + 255) / 256, 256>>>((const int4*)dst, e);
    scan_kernel<<<nb, 1024>>>(n);
    {
        int nGemm = (n + 127) / 128;
        int nFill = ((e >> 2) + 255) / 256;
        gemm1_fill_kernel<<<nGemm + nFill, 256, SMEM1>>>(x, Wc, src, dst, n, e, nGemm);
    }
    agg_kernel  <<<(n + 31) / 32, 256>>>(bc, n);
    gemm2_kernel<<<(n + 63) / 64, 256>>>(Wl, bl, out, n);
}

// round 15
// speedup vs baseline: 1.2737x; 1.1653x over previous
#include <cuda_runtime.h>
#include <cuda_fp16.h>
#include <mma.h>
#include <stdint.h>

using namespace nvcuda;

#define N_NODES 100000
#define N_EDGES 1600000
#define IN_DIM  128
#define HID_DIM 64
#define OUT_DIM 128

// Scratch (allocation-free rule: __device__ globals)
__device__ __align__(16) __half g_hs[(size_t)N_NODES * HID_DIM];   // fp16 messages
__device__ __align__(16) float  g_h2[(size_t)N_NODES * HID_DIM];   // relu'd hidden
__device__ int g_cnt[N_NODES];
__device__ int g_off[N_NODES];
__device__ int g_pos[N_NODES];
__device__ int g_bpub[128];
__device__ int g_csr[N_EDGES];

#define PUB_FLAG 0x40000000

// ---------------------------------------------------------------- f32x2 helpers
__device__ __forceinline__ unsigned long long pack2(float x, float y) {
    unsigned long long r;
    asm("mov.b64 %0, {%1,%2};" : "=l"(r) : "f"(x), "f"(y));
    return r;
}
__device__ __forceinline__ float2 unpack2(unsigned long long v) {
    float2 r;
    asm("mov.b64 {%0,%1}, %2;" : "=f"(r.x), "=f"(r.y) : "l"(v));
    return r;
}
__device__ __forceinline__ void ffma2(unsigned long long& d, unsigned long long a,
                                      unsigned long long b) {
    asm("fma.rn.f32x2 %0, %1, %2, %0;" : "+l"(d) : "l"(a), "l"(b));
}
__device__ __forceinline__ unsigned long long add2(unsigned long long a,
                                                   unsigned long long b) {
    unsigned long long d;
    asm("add.rn.f32x2 %0, %1, %2;" : "=l"(d) : "l"(a), "l"(b));
    return d;
}

// ---------------------------------------------------------------- CSR build
__global__ void zero_kernel(int n) {
    int i = blockIdx.x * blockDim.x + threadIdx.x;
    if (i < n) g_cnt[i] = 0;
    if (i < 128) g_bpub[i] = 0;
}

__global__ void cnt_kernel(const int4* __restrict__ dst4, int e) {
    int i = blockIdx.x * blockDim.x + threadIdx.x;
    int e4 = e >> 2;
    if (i < e4) {
        int4 d = dst4[i];
        atomicAdd(&g_cnt[d.x], 1);
        atomicAdd(&g_cnt[d.y], 1);
        atomicAdd(&g_cnt[d.z], 1);
        atomicAdd(&g_cnt[d.w], 1);
    }
    if (i == 0) {
        const int* d1 = (const int*)dst4;
        for (int j = e4 * 4; j < e; j++) atomicAdd(&g_cnt[d1[j]], 1);
    }
}

// Single-pass exclusive scan (decoupled lookback; all blocks co-resident).
__global__ __launch_bounds__(1024) void scan_kernel(int n) {
    __shared__ int sh[1024];
    __shared__ int red[1024];
    const int t = threadIdx.x;
    const int b = blockIdx.x;
    const int i = b * 1024 + t;
    int v = (i < n) ? g_cnt[i] : 0;
    sh[t] = v;
    __syncthreads();
    #pragma unroll
    for (int d = 1; d < 1024; d <<= 1) {
        int u = (t >= d) ? sh[t - d] : 0;
        __syncthreads();
        sh[t] += u;
        __syncthreads();
    }
    int incl = sh[t];
    if (t == 1023) atomicExch(&g_bpub[b], incl | PUB_FLAG);

    int pv = 0;
    if (t < b) {
        int w;
        do { w = atomicAdd(&g_bpub[t], 0); } while ((w & PUB_FLAG) == 0);
        pv = w & (PUB_FLAG - 1);
    }
    red[t] = pv;
    __syncthreads();
    #pragma unroll
    for (int s = 512; s > 0; s >>= 1) {
        if (t < s) red[t] += red[t + s];
        __syncthreads();
    }
    int prefix = red[0];
    if (i < n) { g_off[i] = prefix + incl - v; g_pos[i] = 0; }
}

// ---------------------------------------------------------------- GEMM1(wmma) + fill
// Blocks [0, nGemm): D[128x64] = Xf16[128x128] @ Wf16[128x64] via wmma m16n16k16,
//   fp32 accumulate. 8 warps = 4(M) x 2(N) grid of 32x32 warp tiles.
//   W staged fp16 in smem once; X staged in two K=64 fp16 chunks; C staged fp32
//   in smem (overlays W/X after compute); epilogue scales by dinv, packs fp16.
// Blocks [nGemm, ...): CSR fill (4 edges/thread).
__global__ __launch_bounds__(256) void gemm1_fill_kernel(const float* __restrict__ x,
                                                         const float* __restrict__ Wc,
                                                         const int* __restrict__ src,
                                                         const int* __restrict__ dst,
                                                         int n, int e, int nGemm) {
    __shared__ __align__(16) char sbuf[36864];
    __half* sW = (__half*)sbuf;              // [128][72] fp16 (18432 B)
    __half* sX = (__half*)(sbuf + 18432);    // [128][72] fp16 chunk (18432 B)
    float*  sC = (float*)sbuf;               // [128][68] fp32 overlay (34816 B)

    if (blockIdx.x >= nGemm) {   // ---- fill part
        int i = (blockIdx.x - nGemm) * 256 + threadIdx.x;
        int e4 = e >> 2;
        if (i < e4) {
            int4 s4 = ((const int4*)src)[i];
            int4 d4 = ((const int4*)dst)[i];
            int p;
            p = g_off[d4.x] + atomicAdd(&g_pos[d4.x], 1); g_csr[p] = s4.x;
            p = g_off[d4.y] + atomicAdd(&g_pos[d4.y], 1); g_csr[p] = s4.y;
            p = g_off[d4.z] + atomicAdd(&g_pos[d4.z], 1); g_csr[p] = s4.z;
            p = g_off[d4.w] + atomicAdd(&g_pos[d4.w], 1); g_csr[p] = s4.w;
        }
        if (i == 0) {
            for (int j = e4 * 4; j < e; j++) {
                int d = dst[j];
                int p = g_off[d] + atomicAdd(&g_pos[d], 1);
                g_csr[p] = src[j];
            }
        }
        return;
    }

    const int t = threadIdx.x;
    const int wid = t >> 5;
    const int warp_m = wid >> 1;   // 0..3  -> rows [warp_m*32, +32)
    const int warp_n = wid & 1;    // 0..1  -> cols [warp_n*32, +32)
    const int rowBase = blockIdx.x * 128;

    const float4* Xg = (const float4*)x;
    const float4* Wg = (const float4*)Wc;

    // ---- stage W: [128][64] fp32 -> sW [128][72] fp16
    #pragma unroll
    for (int i = 0; i < 8; i++) {
        int idx = t + i * 256;           // 0..2047 float4s
        int k = idx >> 4, c4 = idx & 15;
        float4 v = Wg[idx];
        __half2 h01 = __floats2half2_rn(v.x, v.y);
        __half2 h23 = __floats2half2_rn(v.z, v.w);
        uint2 pk;
        pk.x = *(unsigned int*)&h01;
        pk.y = *(unsigned int*)&h23;
        *(uint2*)&sW[k * 72 + c4 * 4] = pk;
        (void)c4;
    }

    wmma::fragment<wmma::accumulator, 16, 16, 16, float> cfrag[2][2];
    #pragma unroll
    for (int i = 0; i < 2; i++)
        #pragma unroll
        for (int j = 0; j < 2; j++) wmma::fill_fragment(cfrag[i][j], 0.0f);

    for (int chunk = 0; chunk < 2; chunk++) {
        __syncthreads();   // sW ready (chunk 0) / sX drained (chunk 1)
        // ---- stage X chunk: rows rowBase..+128, k in [chunk*64, +64) -> sX fp16
        #pragma unroll
        for (int i = 0; i < 8; i++) {
            int idx = t + i * 256;           // 0..2047 float4s
            int r = idx >> 4, c4 = idx & 15;
            int row = rowBase + r;
            if (row >= n) row = n - 1;       // clamp; clamped rows never stored
            float4 v = Xg[(size_t)row * 32 + chunk * 16 + c4];
            __half2 h01 = __floats2half2_rn(v.x, v.y);
            __half2 h23 = __floats2half2_rn(v.z, v.w);
            uint2 pk;
            pk.x = *(unsigned int*)&h01;
            pk.y = *(unsigned int*)&h23;
            *(uint2*)&sX[r * 72 + c4 * 4] = pk;
        }
        __syncthreads();

        #pragma unroll
        for (int ks = 0; ks < 4; ks++) {
            wmma::fragment<wmma::matrix_a, 16, 16, 16, __half, wmma::row_major> afrag[2];
            wmma::fragment<wmma::matrix_b, 16, 16, 16, __half, wmma::row_major> bfrag[2];
            #pragma unroll
            for (int i = 0; i < 2; i++)
                wmma::load_matrix_sync(afrag[i],
                    sX + (warp_m * 32 + i * 16) * 72 + ks * 16, 72);
            #pragma unroll
            for (int j = 0; j < 2; j++)
                wmma::load_matrix_sync(bfrag[j],
                    sW + (chunk * 64 + ks * 16) * 72 + warp_n * 32 + j * 16, 72);
            #pragma unroll
            for (int i = 0; i < 2; i++)
                #pragma unroll
                for (int j = 0; j < 2; j++)
                    wmma::mma_sync(cfrag[i][j], afrag[i], bfrag[j], cfrag[i][j]);
        }
    }

    // ---- epilogue: C frags -> sC (fp32), then dinv-scale + fp16 pack -> g_hs
    __syncthreads();   // sW/sX dead; sC overlay safe
    #pragma unroll
    for (int i = 0; i < 2; i++)
        #pragma unroll
        for (int j = 0; j < 2; j++)
            wmma::store_matrix_sync(
                sC + (warp_m * 32 + i * 16) * 68 + warp_n * 32 + j * 16,
                cfrag[i][j], 68, wmma::mem_row_major);
    __syncthreads();

    {
        int r = t >> 1;              // 0..127
        int hp = t & 1;              // column half: [hp*32, +32)
        int row = rowBase + r;
        if (row < n) {
            float dv = rsqrtf((float)g_cnt[row] + 1.0f);
            const float4* cr = (const float4*)&sC[r * 68 + hp * 32];
            #pragma unroll
            for (int m = 0; m < 4; m++) {
                float4 v0 = cr[m * 2];
                float4 v1 = cr[m * 2 + 1];
                __half2 h0 = __floats2half2_rn(v0.x * dv, v0.y * dv);
                __half2 h1 = __floats2half2_rn(v0.z * dv, v0.w * dv);
                __half2 h2 = __floats2half2_rn(v1.x * dv, v1.y * dv);
                __half2 h3 = __floats2half2_rn(v1.z * dv, v1.w * dv);
                uint4 pk;
                pk.x = *(unsigned int*)&h0;
                pk.y = *(unsigned int*)&h1;
                pk.z = *(unsigned int*)&h2;
                pk.w = *(unsigned int*)&h3;
                ((uint4*)g_hs)[(size_t)row * 8 + hp * 4 + m] = pk;
            }
        }
    }
}

// ---------------------------------------------------------------- aggregate
// 8 threads/node, 32 nodes/block. 4-deep gathers summed pairwise in fp16
// (HADD2 tree), converted once, accumulated fp32.
__global__ __launch_bounds__(256) void agg_kernel(const float* __restrict__ bconv,
                                                  int n) {
    const int t = threadIdx.x;
    const int node = blockIdx.x * 32 + (t >> 3);
    const int c8 = t & 7;
    if (node >= n) return;

    const uint4* hs4 = (const uint4*)g_hs;
    float a[8] = {0,0,0,0,0,0,0,0};
    {
        uint4 v = hs4[(size_t)node * 8 + c8];
        const __half2* hp = (const __half2*)&v;
        #pragma unroll
        for (int m = 0; m < 4; m++) {
            float2 f = __half22float2(hp[m]);
            a[m * 2] += f.x; a[m * 2 + 1] += f.y;
        }
    }
    int cnt = g_cnt[node];
    int beg = g_off[node];
    int end = beg + cnt;
    int j = beg;
    for (; j + 3 < end; j += 4) {
        int s0 = g_csr[j],     s1 = g_csr[j + 1];
        int s2 = g_csr[j + 2], s3 = g_csr[j + 3];
        uint4 v0 = hs4[(size_t)s0 * 8 + c8];
        uint4 v1 = hs4[(size_t)s1 * 8 + c8];
        uint4 v2 = hs4[(size_t)s2 * 8 + c8];
        uint4 v3 = hs4[(size_t)s3 * 8 + c8];
        const __half2* h0 = (const __half2*)&v0;
        const __half2* h1 = (const __half2*)&v1;
        const __half2* h2 = (const __half2*)&v2;
        const __half2* h3 = (const __half2*)&v3;
        #pragma unroll
        for (int m = 0; m < 4; m++) {
            __half2 s01 = __hadd2(h0[m], h1[m]);
            __half2 s23 = __hadd2(h2[m], h3[m]);
            float2 f = __half22float2(__hadd2(s01, s23));
            a[m * 2] += f.x; a[m * 2 + 1] += f.y;
        }
    }
    for (; j < end; j++) {
        int s0 = g_csr[j];
        uint4 v0 = hs4[(size_t)s0 * 8 + c8];
        const __half2* h0 = (const __half2*)&v0;
        #pragma unroll
        for (int m = 0; m < 4; m++) {
            float2 f0 = __half22float2(h0[m]);
            a[m * 2] += f0.x; a[m * 2 + 1] += f0.y;
        }
    }
    float dv = rsqrtf((float)cnt + 1.0f);
    float4 bcv0 = __ldg((const float4*)&bconv[c8 * 8]);
    float4 bcv1 = __ldg((const float4*)&bconv[c8 * 8 + 4]);
    float4 r0, r1;
    r0.x = fmaxf(fmaf(a[0], dv, bcv0.x), 0.f);
    r0.y = fmaxf(fmaf(a[1], dv, bcv0.y), 0.f);
    r0.z = fmaxf(fmaf(a[2], dv, bcv0.z), 0.f);
    r0.w = fmaxf(fmaf(a[3], dv, bcv0.w), 0.f);
    r1.x = fmaxf(fmaf(a[4], dv, bcv1.x), 0.f);
    r1.y = fmaxf(fmaf(a[5], dv, bcv1.y), 0.f);
    r1.z = fmaxf(fmaf(a[6], dv, bcv1.z), 0.f);
    r1.w = fmaxf(fmaf(a[7], dv, bcv1.w), 0.f);
    ((float4*)g_h2)[(size_t)node * 16 + c8 * 2]     = r0;
    ((float4*)g_h2)[(size_t)node * 16 + c8 * 2 + 1] = r1;
}

// ---------------------------------------------------------------- GEMM2
// out = h2 @ Wlin + blin.  Tile M=64, N=128, K=64 in 2 chunks of 32 (f32x2).
__global__ __launch_bounds__(256) void gemm2_kernel(const float* __restrict__ Wlin,
                                                    const float* __restrict__ blin,
                                                    float* __restrict__ out,
                                                    int n) {
    __shared__ float4 Hs[64 * 9];
    __shared__ float4 Ws[32 * 32];
    const int t = threadIdx.x;
    const int rowBase = blockIdx.x * 64;
    const int tr = t & 31;
    const int tc = t >> 5;

    unsigned long long acc[2][8];
    #pragma unroll
    for (int i = 0; i < 2; i++)
        #pragma unroll
        for (int c2 = 0; c2 < 8; c2++) acc[i][c2] = 0ull;

    const float4* Wg = (const float4*)Wlin;
    const float4* Hg = (const float4*)g_h2;

    for (int c = 0; c < 2; c++) {
        if (c) __syncthreads();
        #pragma unroll
        for (int i = 0; i < 4; i++) {
            int idx = t + i * 256;
            int k = idx >> 5, col4 = idx & 31;
            Ws[idx] = Wg[(c * 32 + k) * 32 + col4];
        }
        #pragma unroll
        for (int i = 0; i < 2; i++) {
            int idx = t + i * 256;
            int r = idx >> 3, q = idx & 7;
            int row = rowBase + r;
            float4 v = make_float4(0.f, 0.f, 0.f, 0.f);
            if (row < n) v = Hg[(size_t)row * 16 + c * 8 + q];
            Hs[r * 9 + q] = v;
        }
        __syncthreads();

        #pragma unroll
        for (int kq = 0; kq < 8; kq++) {
            float4 xv[2];
            #pragma unroll
            for (int i = 0; i < 2; i++) xv[i] = Hs[(tr + 32 * i) * 9 + kq];
            #pragma unroll
            for (int kk = 0; kk < 4; kk++) {
                unsigned long long wp[8];
                #pragma unroll
                for (int m = 0; m < 4; m++) {
                    float4 w = Ws[(kq * 4 + kk) * 32 + tc * 4 + m];
                    wp[m * 2]     = pack2(w.x, w.y);
                    wp[m * 2 + 1] = pack2(w.z, w.w);
                }
                #pragma unroll
                for (int i = 0; i < 2; i++) {
                    float s = (kk == 0) ? xv[i].x : (kk == 1) ? xv[i].y
                            : (kk == 2) ? xv[i].z : xv[i].w;
                    unsigned long long ss = pack2(s, s);
                    #pragma unroll
                    for (int c2 = 0; c2 < 8; c2++) ffma2(acc[i][c2], ss, wp[c2]);
                }
            }
        }
    }

    unsigned long long blp[8];
    #pragma unroll
    for (int m = 0; m < 4; m++) {
        float4 b = __ldg((const float4*)&blin[tc * 16 + m * 4]);
        blp[m * 2]     = pack2(b.x, b.y);
        blp[m * 2 + 1] = pack2(b.z, b.w);
    }
    #pragma unroll
    for (int i = 0; i < 2; i++) {
        int row = rowBase + tr + 32 * i;
        if (row < n) {
            size_t off = (size_t)row * 32 + tc * 4;
            #pragma unroll
            for (int m = 0; m < 4; m++) {
                float2 lo = unpack2(add2(acc[i][m * 2],     blp[m * 2]));
                float2 hi = unpack2(add2(acc[i][m * 2 + 1], blp[m * 2 + 1]));
                ((float4*)out)[off + m] = make_float4(lo.x, lo.y, hi.x, hi.y);
            }
        }
    }
}

// ---------------------------------------------------------------- launch
extern "C" void kernel_launch(void* const* d_in, const int* in_sizes, int n_in,
                              void* d_out, int out_size) {
    const float* x  = (const float*)d_in[0];
    const int*   ei = (const int*)  d_in[1];
    const float* Wc = (const float*)d_in[2];
    const float* bc = (const float*)d_in[3];
    const float* Wl = (const float*)d_in[4];
    const float* bl = (const float*)d_in[5];
    float*       out = (float*)d_out;

    const int n = in_sizes[0] / IN_DIM;      // 100000
    const int e = in_sizes[1] / 2;           // 1600000
    const int* src = ei;
    const int* dst = ei + e;
    const int nb = (n + 1023) >> 10;         // 98 (must be <= 128)

    zero_kernel<<<(n + 255) / 256, 256>>>(n);
    cnt_kernel <<<((e >> 2) + 255) / 256, 256>>>((const int4*)dst, e);
    scan_kernel<<<nb, 1024>>>(n);
    {
        int nGemm = (n + 127) / 128;
        int nFill = ((e >> 2) + 255) / 256;
        gemm1_fill_kernel<<<nGemm + nFill, 256>>>(x, Wc, src, dst, n, e, nGemm);
    }
    agg_kernel  <<<(n + 31) / 32, 256>>>(bc, n);
    gemm2_kernel<<<(n + 63) / 64, 256>>>(Wl, bl, out, n);
}

// round 16
// speedup vs baseline: 1.7075x; 1.3406x over previous
#include <cuda_runtime.h>
#include <cuda_fp16.h>
#include <mma.h>
#include <stdint.h>

using namespace nvcuda;

#define N_NODES 100000
#define N_EDGES 1600000
#define IN_DIM  128
#define HID_DIM 64
#define OUT_DIM 128

// Scratch (allocation-free rule: __device__ globals)
__device__ __align__(16) __half g_hs[(size_t)N_NODES * HID_DIM];   // fp16 messages
__device__ __align__(16) __half g_h2[(size_t)N_NODES * HID_DIM];   // fp16 hidden
__device__ __align__(16) float  g_tailC[128 * 128];                // gemm2 tail stage
__device__ int g_cnt[N_NODES];
__device__ int g_off[N_NODES];
__device__ int g_pos[N_NODES];
__device__ int g_bpub[128];
__device__ int g_csr[N_EDGES];

#define PUB_FLAG 0x40000000

// ---------------------------------------------------------------- CSR build
__global__ void zero_kernel(int n) {
    int i = blockIdx.x * blockDim.x + threadIdx.x;
    if (i < n) g_cnt[i] = 0;
    if (i < 128) g_bpub[i] = 0;
}

__global__ void cnt_kernel(const int4* __restrict__ dst4, int e) {
    int i = blockIdx.x * blockDim.x + threadIdx.x;
    int e4 = e >> 2;
    if (i < e4) {
        int4 d = dst4[i];
        atomicAdd(&g_cnt[d.x], 1);
        atomicAdd(&g_cnt[d.y], 1);
        atomicAdd(&g_cnt[d.z], 1);
        atomicAdd(&g_cnt[d.w], 1);
    }
    if (i == 0) {
        const int* d1 = (const int*)dst4;
        for (int j = e4 * 4; j < e; j++) atomicAdd(&g_cnt[d1[j]], 1);
    }
}

// Single-pass exclusive scan (decoupled lookback; all blocks co-resident).
__global__ __launch_bounds__(1024) void scan_kernel(int n) {
    __shared__ int sh[1024];
    __shared__ int red[1024];
    const int t = threadIdx.x;
    const int b = blockIdx.x;
    const int i = b * 1024 + t;
    int v = (i < n) ? g_cnt[i] : 0;
    sh[t] = v;
    __syncthreads();
    #pragma unroll
    for (int d = 1; d < 1024; d <<= 1) {
        int u = (t >= d) ? sh[t - d] : 0;
        __syncthreads();
        sh[t] += u;
        __syncthreads();
    }
    int incl = sh[t];
    if (t == 1023) atomicExch(&g_bpub[b], incl | PUB_FLAG);

    int pv = 0;
    if (t < b) {
        int w;
        do { w = atomicAdd(&g_bpub[t], 0); } while ((w & PUB_FLAG) == 0);
        pv = w & (PUB_FLAG - 1);
    }
    red[t] = pv;
    __syncthreads();
    #pragma unroll
    for (int s = 512; s > 0; s >>= 1) {
        if (t < s) red[t] += red[t + s];
        __syncthreads();
    }
    int prefix = red[0];
    if (i < n) { g_off[i] = prefix + incl - v; g_pos[i] = 0; }
}

// ---------------------------------------------------------------- GEMM1(wmma) + fill
__global__ __launch_bounds__(256) void gemm1_fill_kernel(const float* __restrict__ x,
                                                         const float* __restrict__ Wc,
                                                         const int* __restrict__ src,
                                                         const int* __restrict__ dst,
                                                         int n, int e, int nGemm) {
    __shared__ __align__(16) char sbuf[36864];
    __half* sW = (__half*)sbuf;              // [128][72] fp16
    __half* sX = (__half*)(sbuf + 18432);    // [128][72] fp16 chunk
    float*  sC = (float*)sbuf;               // [128][68] fp32 overlay

    if (blockIdx.x >= nGemm) {   // ---- fill part
        int i = (blockIdx.x - nGemm) * 256 + threadIdx.x;
        int e4 = e >> 2;
        if (i < e4) {
            int4 s4 = ((const int4*)src)[i];
            int4 d4 = ((const int4*)dst)[i];
            int p;
            p = g_off[d4.x] + atomicAdd(&g_pos[d4.x], 1); g_csr[p] = s4.x;
            p = g_off[d4.y] + atomicAdd(&g_pos[d4.y], 1); g_csr[p] = s4.y;
            p = g_off[d4.z] + atomicAdd(&g_pos[d4.z], 1); g_csr[p] = s4.z;
            p = g_off[d4.w] + atomicAdd(&g_pos[d4.w], 1); g_csr[p] = s4.w;
        }
        if (i == 0) {
            for (int j = e4 * 4; j < e; j++) {
                int d = dst[j];
                int p = g_off[d] + atomicAdd(&g_pos[d], 1);
                g_csr[p] = src[j];
            }
        }
        return;
    }

    const int t = threadIdx.x;
    const int wid = t >> 5;
    const int warp_m = wid >> 1;
    const int warp_n = wid & 1;
    const int rowBase = blockIdx.x * 128;

    const float4* Xg = (const float4*)x;
    const float4* Wg = (const float4*)Wc;

    // stage W: [128][64] fp32 -> sW [128][72] fp16
    #pragma unroll
    for (int i = 0; i < 8; i++) {
        int idx = t + i * 256;
        int k = idx >> 4, c4 = idx & 15;
        float4 v = Wg[idx];
        __half2 h01 = __floats2half2_rn(v.x, v.y);
        __half2 h23 = __floats2half2_rn(v.z, v.w);
        uint2 pk;
        pk.x = *(unsigned int*)&h01;
        pk.y = *(unsigned int*)&h23;
        *(uint2*)&sW[k * 72 + c4 * 4] = pk;
    }

    wmma::fragment<wmma::accumulator, 16, 16, 16, float> cfrag[2][2];
    #pragma unroll
    for (int i = 0; i < 2; i++)
        #pragma unroll
        for (int j = 0; j < 2; j++) wmma::fill_fragment(cfrag[i][j], 0.0f);

    for (int chunk = 0; chunk < 2; chunk++) {
        __syncthreads();
        #pragma unroll
        for (int i = 0; i < 8; i++) {
            int idx = t + i * 256;
            int r = idx >> 4, c4 = idx & 15;
            int row = rowBase + r;
            if (row >= n) row = n - 1;
            float4 v = Xg[(size_t)row * 32 + chunk * 16 + c4];
            __half2 h01 = __floats2half2_rn(v.x, v.y);
            __half2 h23 = __floats2half2_rn(v.z, v.w);
            uint2 pk;
            pk.x = *(unsigned int*)&h01;
            pk.y = *(unsigned int*)&h23;
            *(uint2*)&sX[r * 72 + c4 * 4] = pk;
        }
        __syncthreads();

        #pragma unroll
        for (int ks = 0; ks < 4; ks++) {
            wmma::fragment<wmma::matrix_a, 16, 16, 16, __half, wmma::row_major> afrag[2];
            wmma::fragment<wmma::matrix_b, 16, 16, 16, __half, wmma::row_major> bfrag[2];
            #pragma unroll
            for (int i = 0; i < 2; i++)
                wmma::load_matrix_sync(afrag[i],
                    sX + (warp_m * 32 + i * 16) * 72 + ks * 16, 72);
            #pragma unroll
            for (int j = 0; j < 2; j++)
                wmma::load_matrix_sync(bfrag[j],
                    sW + (chunk * 64 + ks * 16) * 72 + warp_n * 32 + j * 16, 72);
            #pragma unroll
            for (int i = 0; i < 2; i++)
                #pragma unroll
                for (int j = 0; j < 2; j++)
                    wmma::mma_sync(cfrag[i][j], afrag[i], bfrag[j], cfrag[i][j]);
        }
    }

    __syncthreads();
    #pragma unroll
    for (int i = 0; i < 2; i++)
        #pragma unroll
        for (int j = 0; j < 2; j++)
            wmma::store_matrix_sync(
                sC + (warp_m * 32 + i * 16) * 68 + warp_n * 32 + j * 16,
                cfrag[i][j], 68, wmma::mem_row_major);
    __syncthreads();

    {
        int r = t >> 1;
        int hp = t & 1;
        int row = rowBase + r;
        if (row < n) {
            float dv = rsqrtf((float)g_cnt[row] + 1.0f);
            const float4* cr = (const float4*)&sC[r * 68 + hp * 32];
            #pragma unroll
            for (int m = 0; m < 4; m++) {
                float4 v0 = cr[m * 2];
                float4 v1 = cr[m * 2 + 1];
                __half2 h0 = __floats2half2_rn(v0.x * dv, v0.y * dv);
                __half2 h1 = __floats2half2_rn(v0.z * dv, v0.w * dv);
                __half2 h2 = __floats2half2_rn(v1.x * dv, v1.y * dv);
                __half2 h3 = __floats2half2_rn(v1.z * dv, v1.w * dv);
                uint4 pk;
                pk.x = *(unsigned int*)&h0;
                pk.y = *(unsigned int*)&h1;
                pk.z = *(unsigned int*)&h2;
                pk.w = *(unsigned int*)&h3;
                ((uint4*)g_hs)[(size_t)row * 8 + hp * 4 + m] = pk;
            }
        }
    }
}

// ---------------------------------------------------------------- aggregate
// 8 threads/node, 32 nodes/block. HADD2 pairwise tree, fp32 accumulate,
// h2 stored fp16 (one uint4 per thread).
__global__ __launch_bounds__(256) void agg_kernel(const float* __restrict__ bconv,
                                                  int n) {
    const int t = threadIdx.x;
    const int node = blockIdx.x * 32 + (t >> 3);
    const int c8 = t & 7;
    if (node >= n) return;

    const uint4* hs4 = (const uint4*)g_hs;
    float a[8] = {0,0,0,0,0,0,0,0};
    {
        uint4 v = hs4[(size_t)node * 8 + c8];
        const __half2* hp = (const __half2*)&v;
        #pragma unroll
        for (int m = 0; m < 4; m++) {
            float2 f = __half22float2(hp[m]);
            a[m * 2] += f.x; a[m * 2 + 1] += f.y;
        }
    }
    int cnt = g_cnt[node];
    int beg = g_off[node];
    int end = beg + cnt;
    int j = beg;
    for (; j + 3 < end; j += 4) {
        int s0 = g_csr[j],     s1 = g_csr[j + 1];
        int s2 = g_csr[j + 2], s3 = g_csr[j + 3];
        uint4 v0 = hs4[(size_t)s0 * 8 + c8];
        uint4 v1 = hs4[(size_t)s1 * 8 + c8];
        uint4 v2 = hs4[(size_t)s2 * 8 + c8];
        uint4 v3 = hs4[(size_t)s3 * 8 + c8];
        const __half2* h0 = (const __half2*)&v0;
        const __half2* h1 = (const __half2*)&v1;
        const __half2* h2 = (const __half2*)&v2;
        const __half2* h3 = (const __half2*)&v3;
        #pragma unroll
        for (int m = 0; m < 4; m++) {
            __half2 s01 = __hadd2(h0[m], h1[m]);
            __half2 s23 = __hadd2(h2[m], h3[m]);
            float2 f = __half22float2(__hadd2(s01, s23));
            a[m * 2] += f.x; a[m * 2 + 1] += f.y;
        }
    }
    for (; j < end; j++) {
        int s0 = g_csr[j];
        uint4 v0 = hs4[(size_t)s0 * 8 + c8];
        const __half2* h0 = (const __half2*)&v0;
        #pragma unroll
        for (int m = 0; m < 4; m++) {
            float2 f0 = __half22float2(h0[m]);
            a[m * 2] += f0.x; a[m * 2 + 1] += f0.y;
        }
    }
    float dv = rsqrtf((float)cnt + 1.0f);
    float4 bcv0 = __ldg((const float4*)&bconv[c8 * 8]);
    float4 bcv1 = __ldg((const float4*)&bconv[c8 * 8 + 4]);
    __half2 o0 = __floats2half2_rn(fmaxf(fmaf(a[0], dv, bcv0.x), 0.f),
                                   fmaxf(fmaf(a[1], dv, bcv0.y), 0.f));
    __half2 o1 = __floats2half2_rn(fmaxf(fmaf(a[2], dv, bcv0.z), 0.f),
                                   fmaxf(fmaf(a[3], dv, bcv0.w), 0.f));
    __half2 o2 = __floats2half2_rn(fmaxf(fmaf(a[4], dv, bcv1.x), 0.f),
                                   fmaxf(fmaf(a[5], dv, bcv1.y), 0.f));
    __half2 o3 = __floats2half2_rn(fmaxf(fmaf(a[6], dv, bcv1.z), 0.f),
                                   fmaxf(fmaf(a[7], dv, bcv1.w), 0.f));
    uint4 pk;
    pk.x = *(unsigned int*)&o0;
    pk.y = *(unsigned int*)&o1;
    pk.z = *(unsigned int*)&o2;
    pk.w = *(unsigned int*)&o3;
    ((uint4*)g_h2)[(size_t)node * 8 + c8] = pk;
}

// ---------------------------------------------------------------- GEMM2 (wmma)
// out[128x128 tile] = H_f16[128x64] @ Wl_f16[64x128] + blin.
// 8 warps = 4(M) x 2(N), each 32x64 (cfrag[2][4]). Bias folded in by loading
// accumulator fragments from a 16-row broadcast bias tile. Full blocks store
// fragments straight to global out; the single tail block stages via g_tailC.
__global__ __launch_bounds__(256) void gemm2_kernel(const float* __restrict__ Wlin,
                                                    const float* __restrict__ blin,
                                                    float* __restrict__ out,
                                                    int n) {
    __shared__ __align__(16) __half sH[128 * 72];     // 18432 B
    __shared__ __align__(16) __half sW[64 * 136];     // 17408 B
    __shared__ __align__(16) float  sBias[16 * 136];  // 8704 B
    const int t = threadIdx.x;
    const int wid = t >> 5;
    const int warp_m = wid >> 1;   // 0..3
    const int warp_n = wid & 1;    // 0..1
    const int rowBase = blockIdx.x * 128;
    const bool fullTile = (rowBase + 128 <= n);

    // stage Wl: [64][128] fp32 -> sW fp16 (stride 136)
    const float4* Wg = (const float4*)Wlin;
    #pragma unroll
    for (int i = 0; i < 8; i++) {
        int idx = t + i * 256;           // 0..2047 float4s
        int k = idx >> 5, c4 = idx & 31;
        float4 v = Wg[idx];
        __half2 h01 = __floats2half2_rn(v.x, v.y);
        __half2 h23 = __floats2half2_rn(v.z, v.w);
        uint2 pk;
        pk.x = *(unsigned int*)&h01;
        pk.y = *(unsigned int*)&h23;
        *(uint2*)&sW[k * 136 + c4 * 4] = pk;
    }
    // stage bias tile: 16 rows, each = blin
    #pragma unroll
    for (int i = 0; i < 8; i++) {
        int idx = t + i * 256;           // 0..2047
        int r = idx >> 7, c = idx & 127;
        sBias[r * 136 + c] = __ldg(&blin[c]);
    }
    // stage H: [128][64] fp16 (uint4 = 8 halves per transfer)
    const uint4* Hg = (const uint4*)g_h2;
    #pragma unroll
    for (int i = 0; i < 4; i++) {
        int idx = t + i * 256;           // 0..1023
        int r = idx >> 3, q = idx & 7;
        int row = rowBase + r;
        if (row >= n) row = n - 1;       // clamp; tail handled at store
        *(uint4*)&sH[r * 72 + q * 8] = Hg[(size_t)row * 8 + q];
    }
    __syncthreads();

    // accumulators initialized with bias
    wmma::fragment<wmma::accumulator, 16, 16, 16, float> cfrag[2][4];
    #pragma unroll
    for (int i = 0; i < 2; i++)
        #pragma unroll
        for (int j = 0; j < 4; j++)
            wmma::load_matrix_sync(cfrag[i][j],
                sBias + warp_n * 64 + j * 16, 136, wmma::mem_row_major);

    #pragma unroll
    for (int ks = 0; ks < 4; ks++) {
        wmma::fragment<wmma::matrix_a, 16, 16, 16, __half, wmma::row_major> afrag[2];
        wmma::fragment<wmma::matrix_b, 16, 16, 16, __half, wmma::row_major> bfrag[4];
        #pragma unroll
        for (int i = 0; i < 2; i++)
            wmma::load_matrix_sync(afrag[i],
                sH + (warp_m * 32 + i * 16) * 72 + ks * 16, 72);
        #pragma unroll
        for (int j = 0; j < 4; j++)
            wmma::load_matrix_sync(bfrag[j],
                sW + (ks * 16) * 136 + warp_n * 64 + j * 16, 136);
        #pragma unroll
        for (int i = 0; i < 2; i++)
            #pragma unroll
            for (int j = 0; j < 4; j++)
                wmma::mma_sync(cfrag[i][j], afrag[i], bfrag[j], cfrag[i][j]);
    }

    if (fullTile) {
        #pragma unroll
        for (int i = 0; i < 2; i++)
            #pragma unroll
            for (int j = 0; j < 4; j++)
                wmma::store_matrix_sync(
                    out + (size_t)(rowBase + warp_m * 32 + i * 16) * 128
                        + warp_n * 64 + j * 16,
                    cfrag[i][j], 128, wmma::mem_row_major);
    } else {
        // single tail block: stage to scratch, masked copy
        #pragma unroll
        for (int i = 0; i < 2; i++)
            #pragma unroll
            for (int j = 0; j < 4; j++)
                wmma::store_matrix_sync(
                    g_tailC + (warp_m * 32 + i * 16) * 128 + warp_n * 64 + j * 16,
                    cfrag[i][j], 128, wmma::mem_row_major);
        __syncthreads();
        int valid = n - rowBase;
        for (int idx = t; idx < valid * 32; idx += 256) {
            int r = idx >> 5, c4 = idx & 31;
            ((float4*)out)[(size_t)(rowBase + r) * 32 + c4] =
                ((const float4*)g_tailC)[r * 32 + c4];
        }
    }
}

// ---------------------------------------------------------------- launch
extern "C" void kernel_launch(void* const* d_in, const int* in_sizes, int n_in,
                              void* d_out, int out_size) {
    const float* x  = (const float*)d_in[0];
    const int*   ei = (const int*)  d_in[1];
    const float* Wc = (const float*)d_in[2];
    const float* bc = (const float*)d_in[3];
    const float* Wl = (const float*)d_in[4];
    const float* bl = (const float*)d_in[5];
    float*       out = (float*)d_out;

    const int n = in_sizes[0] / IN_DIM;      // 100000
    const int e = in_sizes[1] / 2;           // 1600000
    const int* src = ei;
    const int* dst = ei + e;
    const int nb = (n + 1023) >> 10;         // 98 (must be <= 128)

    zero_kernel<<<(n + 255) / 256, 256>>>(n);
    cnt_kernel <<<((e >> 2) + 255) / 256, 256>>>((const int4*)dst, e);
    scan_kernel<<<nb, 1024>>>(n);
    {
        int nGemm = (n + 127) / 128;
        int nFill = ((e >> 2) + 255) / 256;
        gemm1_fill_kernel<<<nGemm + nFill, 256>>>(x, Wc, src, dst, n, e, nGemm);
    }
    agg_kernel  <<<(n + 31) / 32, 256>>>(bc, n);
    gemm2_kernel<<<(n + 127) / 128, 256>>>(Wl, bl, out, n);
}

// round 17
// speedup vs baseline: 1.8075x; 1.0585x over previous
#include <cuda_runtime.h>
#include <cuda_fp16.h>
#include <mma.h>
#include <stdint.h>

using namespace nvcuda;

#define N_NODES 100000
#define N_EDGES 1600000
#define IN_DIM  128
#define HID_DIM 64
#define OUT_DIM 128

// Scratch (allocation-free rule: __device__ globals)
__device__ __align__(16) __half g_hs[(size_t)N_NODES * HID_DIM];   // fp16 messages
__device__ __align__(16) __half g_h2[(size_t)N_NODES * HID_DIM];   // fp16 hidden
__device__ __align__(16) float  g_tailC[128 * 128];                // gemm2 tail stage
__device__ int g_cnt[N_NODES];
__device__ int g_off[N_NODES];
__device__ int g_bpub[128];
__device__ int g_csr[N_EDGES];
__device__ int g_rank[N_EDGES];    // edge's rank among same-dst edges

#define PUB_FLAG 0x40000000

// ---------------------------------------------------------------- CSR build
__global__ void zero_kernel(int n) {
    int i = blockIdx.x * blockDim.x + threadIdx.x;
    if (i < n) g_cnt[i] = 0;
    if (i < 128) g_bpub[i] = 0;
}

// count + record each edge's rank (atomicAdd return value) — fill needs no atomics
__global__ void cnt_kernel(const int4* __restrict__ dst4, int e) {
    int i = blockIdx.x * blockDim.x + threadIdx.x;
    int e4 = e >> 2;
    if (i < e4) {
        int4 d = dst4[i];
        int4 r;
        r.x = atomicAdd(&g_cnt[d.x], 1);
        r.y = atomicAdd(&g_cnt[d.y], 1);
        r.z = atomicAdd(&g_cnt[d.z], 1);
        r.w = atomicAdd(&g_cnt[d.w], 1);
        ((int4*)g_rank)[i] = r;
    }
    if (i == 0) {
        const int* d1 = (const int*)dst4;
        for (int j = e4 * 4; j < e; j++) g_rank[j] = atomicAdd(&g_cnt[d1[j]], 1);
    }
}

// Single-pass exclusive scan: shuffle warp-scans + decoupled lookback.
__global__ __launch_bounds__(1024) void scan_kernel(int n) {
    __shared__ int wsum[32];
    __shared__ int prefix_s;
    const int t = threadIdx.x;
    const int b = blockIdx.x;
    const int i = b * 1024 + t;
    const int lane = t & 31;
    const int w = t >> 5;

    int v = (i < n) ? g_cnt[i] : 0;
    int s = v;
    #pragma unroll
    for (int d = 1; d < 32; d <<= 1) {
        int u = __shfl_up_sync(0xFFFFFFFFu, s, d);
        if (lane >= d) s += u;
    }
    if (lane == 31) wsum[w] = s;
    if (t == 0) prefix_s = 0;
    __syncthreads();
    if (w == 0) {
        int ws = wsum[lane];
        #pragma unroll
        for (int d = 1; d < 32; d <<= 1) {
            int u = __shfl_up_sync(0xFFFFFFFFu, ws, d);
            if (lane >= d) ws += u;
        }
        wsum[lane] = ws;
    }
    __syncthreads();
    int incl = s + (w > 0 ? wsum[w - 1] : 0);
    if (t == 1023) atomicExch(&g_bpub[b], incl | PUB_FLAG);

    // lookback: thread t spins on predecessor block t, reduce across block
    int pv = 0;
    if (t < b) {
        int wv;
        do { wv = atomicAdd(&g_bpub[t], 0); } while ((wv & PUB_FLAG) == 0);
        pv = wv & (PUB_FLAG - 1);
    }
    #pragma unroll
    for (int d = 16; d > 0; d >>= 1) pv += __shfl_down_sync(0xFFFFFFFFu, pv, d);
    if (lane == 0 && pv != 0) atomicAdd(&prefix_s, pv);
    __syncthreads();
    if (i < n) g_off[i] = prefix_s + incl - v;
}

// ---------------------------------------------------------------- GEMM1(wmma) + fill
__global__ __launch_bounds__(256) void gemm1_fill_kernel(const float* __restrict__ x,
                                                         const float* __restrict__ Wc,
                                                         const int* __restrict__ src,
                                                         const int* __restrict__ dst,
                                                         int n, int e, int nGemm) {
    __shared__ __align__(16) char sbuf[36864];
    __half* sW = (__half*)sbuf;              // [128][72] fp16
    __half* sX = (__half*)(sbuf + 18432);    // [128][72] fp16 chunk
    float*  sC = (float*)sbuf;               // [128][68] fp32 overlay

    if (blockIdx.x >= nGemm) {   // ---- fill part: atomic-free scatter
        int i = (blockIdx.x - nGemm) * 256 + threadIdx.x;
        int e4 = e >> 2;
        if (i < e4) {
            int4 s4 = ((const int4*)src)[i];
            int4 d4 = ((const int4*)dst)[i];
            int4 r4 = ((const int4*)g_rank)[i];
            g_csr[g_off[d4.x] + r4.x] = s4.x;
            g_csr[g_off[d4.y] + r4.y] = s4.y;
            g_csr[g_off[d4.z] + r4.z] = s4.z;
            g_csr[g_off[d4.w] + r4.w] = s4.w;
        }
        if (i == 0) {
            for (int j = e4 * 4; j < e; j++)
                g_csr[g_off[dst[j]] + g_rank[j]] = src[j];
        }
        return;
    }

    const int t = threadIdx.x;
    const int wid = t >> 5;
    const int warp_m = wid >> 1;
    const int warp_n = wid & 1;
    const int rowBase = blockIdx.x * 128;

    const float4* Xg = (const float4*)x;
    const float4* Wg = (const float4*)Wc;

    // stage W: [128][64] fp32 -> sW [128][72] fp16
    #pragma unroll
    for (int i = 0; i < 8; i++) {
        int idx = t + i * 256;
        int k = idx >> 4, c4 = idx & 15;
        float4 v = Wg[idx];
        __half2 h01 = __floats2half2_rn(v.x, v.y);
        __half2 h23 = __floats2half2_rn(v.z, v.w);
        uint2 pk;
        pk.x = *(unsigned int*)&h01;
        pk.y = *(unsigned int*)&h23;
        *(uint2*)&sW[k * 72 + c4 * 4] = pk;
    }

    wmma::fragment<wmma::accumulator, 16, 16, 16, float> cfrag[2][2];
    #pragma unroll
    for (int i = 0; i < 2; i++)
        #pragma unroll
        for (int j = 0; j < 2; j++) wmma::fill_fragment(cfrag[i][j], 0.0f);

    for (int chunk = 0; chunk < 2; chunk++) {
        __syncthreads();
        #pragma unroll
        for (int i = 0; i < 8; i++) {
            int idx = t + i * 256;
            int r = idx >> 4, c4 = idx & 15;
            int row = rowBase + r;
            if (row >= n) row = n - 1;
            float4 v = Xg[(size_t)row * 32 + chunk * 16 + c4];
            __half2 h01 = __floats2half2_rn(v.x, v.y);
            __half2 h23 = __floats2half2_rn(v.z, v.w);
            uint2 pk;
            pk.x = *(unsigned int*)&h01;
            pk.y = *(unsigned int*)&h23;
            *(uint2*)&sX[r * 72 + c4 * 4] = pk;
        }
        __syncthreads();

        #pragma unroll
        for (int ks = 0; ks < 4; ks++) {
            wmma::fragment<wmma::matrix_a, 16, 16, 16, __half, wmma::row_major> afrag[2];
            wmma::fragment<wmma::matrix_b, 16, 16, 16, __half, wmma::row_major> bfrag[2];
            #pragma unroll
            for (int i = 0; i < 2; i++)
                wmma::load_matrix_sync(afrag[i],
                    sX + (warp_m * 32 + i * 16) * 72 + ks * 16, 72);
            #pragma unroll
            for (int j = 0; j < 2; j++)
                wmma::load_matrix_sync(bfrag[j],
                    sW + (chunk * 64 + ks * 16) * 72 + warp_n * 32 + j * 16, 72);
            #pragma unroll
            for (int i = 0; i < 2; i++)
                #pragma unroll
                for (int j = 0; j < 2; j++)
                    wmma::mma_sync(cfrag[i][j], afrag[i], bfrag[j], cfrag[i][j]);
        }
    }

    __syncthreads();
    #pragma unroll
    for (int i = 0; i < 2; i++)
        #pragma unroll
        for (int j = 0; j < 2; j++)
            wmma::store_matrix_sync(
                sC + (warp_m * 32 + i * 16) * 68 + warp_n * 32 + j * 16,
                cfrag[i][j], 68, wmma::mem_row_major);
    __syncthreads();

    {
        int r = t >> 1;
        int hp = t & 1;
        int row = rowBase + r;
        if (row < n) {
            float dv = rsqrtf((float)g_cnt[row] + 1.0f);
            const float4* cr = (const float4*)&sC[r * 68 + hp * 32];
            #pragma unroll
            for (int m = 0; m < 4; m++) {
                float4 v0 = cr[m * 2];
                float4 v1 = cr[m * 2 + 1];
                __half2 h0 = __floats2half2_rn(v0.x * dv, v0.y * dv);
                __half2 h1 = __floats2half2_rn(v0.z * dv, v0.w * dv);
                __half2 h2 = __floats2half2_rn(v1.x * dv, v1.y * dv);
                __half2 h3 = __floats2half2_rn(v1.z * dv, v1.w * dv);
                uint4 pk;
                pk.x = *(unsigned int*)&h0;
                pk.y = *(unsigned int*)&h1;
                pk.z = *(unsigned int*)&h2;
                pk.w = *(unsigned int*)&h3;
                ((uint4*)g_hs)[(size_t)row * 8 + hp * 4 + m] = pk;
            }
        }
    }
}

// ---------------------------------------------------------------- aggregate
// 8 threads/node, 32 nodes/block. HADD2 pairwise tree, fp32 accumulate,
// h2 stored fp16 (one uint4 per thread).
__global__ __launch_bounds__(256) void agg_kernel(const float* __restrict__ bconv,
                                                  int n) {
    const int t = threadIdx.x;
    const int node = blockIdx.x * 32 + (t >> 3);
    const int c8 = t & 7;
    if (node >= n) return;

    const uint4* hs4 = (const uint4*)g_hs;
    float a[8] = {0,0,0,0,0,0,0,0};
    {
        uint4 v = hs4[(size_t)node * 8 + c8];
        const __half2* hp = (const __half2*)&v;
        #pragma unroll
        for (int m = 0; m < 4; m++) {
            float2 f = __half22float2(hp[m]);
            a[m * 2] += f.x; a[m * 2 + 1] += f.y;
        }
    }
    int cnt = g_cnt[node];
    int beg = g_off[node];
    int end = beg + cnt;
    int j = beg;
    for (; j + 3 < end; j += 4) {
        int s0 = g_csr[j],     s1 = g_csr[j + 1];
        int s2 = g_csr[j + 2], s3 = g_csr[j + 3];
        uint4 v0 = hs4[(size_t)s0 * 8 + c8];
        uint4 v1 = hs4[(size_t)s1 * 8 + c8];
        uint4 v2 = hs4[(size_t)s2 * 8 + c8];
        uint4 v3 = hs4[(size_t)s3 * 8 + c8];
        const __half2* h0 = (const __half2*)&v0;
        const __half2* h1 = (const __half2*)&v1;
        const __half2* h2 = (const __half2*)&v2;
        const __half2* h3 = (const __half2*)&v3;
        #pragma unroll
        for (int m = 0; m < 4; m++) {
            __half2 s01 = __hadd2(h0[m], h1[m]);
            __half2 s23 = __hadd2(h2[m], h3[m]);
            float2 f = __half22float2(__hadd2(s01, s23));
            a[m * 2] += f.x; a[m * 2 + 1] += f.y;
        }
    }
    for (; j < end; j++) {
        int s0 = g_csr[j];
        uint4 v0 = hs4[(size_t)s0 * 8 + c8];
        const __half2* h0 = (const __half2*)&v0;
        #pragma unroll
        for (int m = 0; m < 4; m++) {
            float2 f0 = __half22float2(h0[m]);
            a[m * 2] += f0.x; a[m * 2 + 1] += f0.y;
        }
    }
    float dv = rsqrtf((float)cnt + 1.0f);
    float4 bcv0 = __ldg((const float4*)&bconv[c8 * 8]);
    float4 bcv1 = __ldg((const float4*)&bconv[c8 * 8 + 4]);
    __half2 o0 = __floats2half2_rn(fmaxf(fmaf(a[0], dv, bcv0.x), 0.f),
                                   fmaxf(fmaf(a[1], dv, bcv0.y), 0.f));
    __half2 o1 = __floats2half2_rn(fmaxf(fmaf(a[2], dv, bcv0.z), 0.f),
                                   fmaxf(fmaf(a[3], dv, bcv0.w), 0.f));
    __half2 o2 = __floats2half2_rn(fmaxf(fmaf(a[4], dv, bcv1.x), 0.f),
                                   fmaxf(fmaf(a[5], dv, bcv1.y), 0.f));
    __half2 o3 = __floats2half2_rn(fmaxf(fmaf(a[6], dv, bcv1.z), 0.f),
                                   fmaxf(fmaf(a[7], dv, bcv1.w), 0.f));
    uint4 pk;
    pk.x = *(unsigned int*)&o0;
    pk.y = *(unsigned int*)&o1;
    pk.z = *(unsigned int*)&o2;
    pk.w = *(unsigned int*)&o3;
    ((uint4*)g_h2)[(size_t)node * 8 + c8] = pk;
}

// ---------------------------------------------------------------- GEMM2 (wmma)
__global__ __launch_bounds__(256) void gemm2_kernel(const float* __restrict__ Wlin,
                                                    const float* __restrict__ blin,
                                                    float* __restrict__ out,
                                                    int n) {
    __shared__ __align__(16) __half sH[128 * 72];     // 18432 B
    __shared__ __align__(16) __half sW[64 * 136];     // 17408 B
    __shared__ __align__(16) float  sBias[16 * 136];  // 8704 B
    const int t = threadIdx.x;
    const int wid = t >> 5;
    const int warp_m = wid >> 1;
    const int warp_n = wid & 1;
    const int rowBase = blockIdx.x * 128;
    const bool fullTile = (rowBase + 128 <= n);

    const float4* Wg = (const float4*)Wlin;
    #pragma unroll
    for (int i = 0; i < 8; i++) {
        int idx = t + i * 256;
        int k = idx >> 5, c4 = idx & 31;
        float4 v = Wg[idx];
        __half2 h01 = __floats2half2_rn(v.x, v.y);
        __half2 h23 = __floats2half2_rn(v.z, v.w);
        uint2 pk;
        pk.x = *(unsigned int*)&h01;
        pk.y = *(unsigned int*)&h23;
        *(uint2*)&sW[k * 136 + c4 * 4] = pk;
    }
    #pragma unroll
    for (int i = 0; i < 8; i++) {
        int idx = t + i * 256;
        int r = idx >> 7, c = idx & 127;
        sBias[r * 136 + c] = __ldg(&blin[c]);
    }
    const uint4* Hg = (const uint4*)g_h2;
    #pragma unroll
    for (int i = 0; i < 4; i++) {
        int idx = t + i * 256;
        int r = idx >> 3, q = idx & 7;
        int row = rowBase + r;
        if (row >= n) row = n - 1;
        *(uint4*)&sH[r * 72 + q * 8] = Hg[(size_t)row * 8 + q];
    }
    __syncthreads();

    wmma::fragment<wmma::accumulator, 16, 16, 16, float> cfrag[2][4];
    #pragma unroll
    for (int i = 0; i < 2; i++)
        #pragma unroll
        for (int j = 0; j < 4; j++)
            wmma::load_matrix_sync(cfrag[i][j],
                sBias + warp_n * 64 + j * 16, 136, wmma::mem_row_major);

    #pragma unroll
    for (int ks = 0; ks < 4; ks++) {
        wmma::fragment<wmma::matrix_a, 16, 16, 16, __half, wmma::row_major> afrag[2];
        wmma::fragment<wmma::matrix_b, 16, 16, 16, __half, wmma::row_major> bfrag[4];
        #pragma unroll
        for (int i = 0; i < 2; i++)
            wmma::load_matrix_sync(afrag[i],
                sH + (warp_m * 32 + i * 16) * 72 + ks * 16, 72);
        #pragma unroll
        for (int j = 0; j < 4; j++)
            wmma::load_matrix_sync(bfrag[j],
                sW + (ks * 16) * 136 + warp_n * 64 + j * 16, 136);
        #pragma unroll
        for (int i = 0; i < 2; i++)
            #pragma unroll
            for (int j = 0; j < 4; j++)
                wmma::mma_sync(cfrag[i][j], afrag[i], bfrag[j], cfrag[i][j]);
    }

    if (fullTile) {
        #pragma unroll
        for (int i = 0; i < 2; i++)
            #pragma unroll
            for (int j = 0; j < 4; j++)
                wmma::store_matrix_sync(
                    out + (size_t)(rowBase + warp_m * 32 + i * 16) * 128
                        + warp_n * 64 + j * 16,
                    cfrag[i][j], 128, wmma::mem_row_major);
    } else {
        #pragma unroll
        for (int i = 0; i < 2; i++)
            #pragma unroll
            for (int j = 0; j < 4; j++)
                wmma::store_matrix_sync(
                    g_tailC + (warp_m * 32 + i * 16) * 128 + warp_n * 64 + j * 16,
                    cfrag[i][j], 128, wmma::mem_row_major);
        __syncthreads();
        int valid = n - rowBase;
        for (int idx = t; idx < valid * 32; idx += 256) {
            int r = idx >> 5, c4 = idx & 31;
            ((float4*)out)[(size_t)(rowBase + r) * 32 + c4] =
                ((const float4*)g_tailC)[r * 32 + c4];
        }
    }
}

// ---------------------------------------------------------------- launch
extern "C" void kernel_launch(void* const* d_in, const int* in_sizes, int n_in,
                              void* d_out, int out_size) {
    const float* x  = (const float*)d_in[0];
    const int*   ei = (const int*)  d_in[1];
    const float* Wc = (const float*)d_in[2];
    const float* bc = (const float*)d_in[3];
    const float* Wl = (const float*)d_in[4];
    const float* bl = (const float*)d_in[5];
    float*       out = (float*)d_out;

    const int n = in_sizes[0] / IN_DIM;      // 100000
    const int e = in_sizes[1] / 2;           // 1600000
    const int* src = ei;
    const int* dst = ei + e;
    const int nb = (n + 1023) >> 10;         // 98 (must be <= 128)

    zero_kernel<<<(n + 255) / 256, 256>>>(n);
    cnt_kernel <<<((e >> 2) + 255) / 256, 256>>>((const int4*)dst, e);
    scan_kernel<<<nb, 1024>>>(n);
    {
        int nGemm = (n + 127) / 128;
        int nFill = ((e >> 2) + 255) / 256;
        gemm1_fill_kernel<<<nGemm + nFill, 256>>>(x, Wc, src, dst, n, e, nGemm);
    }
    agg_kernel  <<<(n + 31) / 32, 256>>>(bc, n);
    gemm2_kernel<<<(n + 127) / 128, 256>>>(Wl, bl, out, n);
}